// round 7
// baseline (speedup 1.0000x reference)
#include <cuda_runtime.h>
#include <cuda_bf16.h>
#include <stdint.h>
#include <math.h>

// Problem constants
#define B_    2
#define S_    1024
#define H_    4096
#define NH_   32
#define HD_   128
#define M_    2048
#define NQKV_ 12288

// ---------------- device scratch (no runtime allocation) ----------------
__device__ float g_qkv[(size_t)M_ * NQKV_];
__device__ __nv_bfloat16 g_Ah[(size_t)M_ * H_];
__device__ __nv_bfloat16 g_Al[(size_t)M_ * H_];
__device__ __nv_bfloat16 g_Bqh[(size_t)NQKV_ * H_];
__device__ __nv_bfloat16 g_Bql[(size_t)NQKV_ * H_];
__device__ __nv_bfloat16 g_Bdh[(size_t)H_ * H_];
__device__ __nv_bfloat16 g_Bdl[(size_t)H_ * H_];
__device__ __nv_bfloat16 g_Ch[(size_t)M_ * H_];
__device__ __nv_bfloat16 g_Cl[(size_t)M_ * H_];

// ---------------- PTX helpers (portable, non-'a' features only) ----------------
__device__ __forceinline__ uint32_t smem_u32(const void* p) {
    uint32_t a;
    asm("{ .reg .u64 t; cvta.to.shared.u64 t, %1; cvt.u32.u64 %0, t; }" : "=r"(a) : "l"(p));
    return a;
}
__device__ __forceinline__ void cp_async16(uint32_t dst_smem, const void* src) {
    asm volatile("cp.async.cg.shared.global [%0], [%1], 16;"
                 :: "r"(dst_smem), "l"(src) : "memory");
}
__device__ __forceinline__ void cp_commit() {
    asm volatile("cp.async.commit_group;" ::: "memory");
}
__device__ __forceinline__ void cp_wait1() {
    asm volatile("cp.async.wait_group 1;" ::: "memory");
}
__device__ __forceinline__ void ldsm4(uint32_t* r, uint32_t addr) {
    asm volatile("ldmatrix.sync.aligned.m8n8.x4.shared.b16 {%0,%1,%2,%3}, [%4];"
                 : "=r"(r[0]), "=r"(r[1]), "=r"(r[2]), "=r"(r[3]) : "r"(addr));
}
__device__ __forceinline__ void ldsm4t(uint32_t* r, uint32_t addr) {
    asm volatile("ldmatrix.sync.aligned.m8n8.x4.trans.shared.b16 {%0,%1,%2,%3}, [%4];"
                 : "=r"(r[0]), "=r"(r[1]), "=r"(r[2]), "=r"(r[3]) : "r"(addr));
}
__device__ __forceinline__ void mma_bf16(float* d, const uint32_t* a, const uint32_t* b) {
    asm volatile(
        "mma.sync.aligned.m16n8k16.row.col.f32.bf16.bf16.f32 "
        "{%0,%1,%2,%3}, {%4,%5,%6,%7}, {%8,%9}, {%0,%1,%2,%3};"
        : "+f"(d[0]), "+f"(d[1]), "+f"(d[2]), "+f"(d[3])
        : "r"(a[0]), "r"(a[1]), "r"(a[2]), "r"(a[3]), "r"(b[0]), "r"(b[1]));
}
// pack two floats to bf16x2: low half = lo, high half = hi
__device__ __forceinline__ uint32_t pack_bf16(float lo, float hi) {
    uint32_t r;
    asm("cvt.rn.bf16x2.f32 %0, %1, %2;" : "=r"(r) : "f"(hi), "f"(lo));
    return r;
}
__device__ __forceinline__ float2 unpack_bf16(uint32_t v) {
    __nv_bfloat162 h = *reinterpret_cast<__nv_bfloat162*>(&v);
    return __bfloat1622float2(h);
}

// ---------------- split helpers ----------------
__device__ __forceinline__ void split1(float f, __nv_bfloat16& h, __nv_bfloat16& l) {
    h = __float2bfloat16(f);
    l = __float2bfloat16(f - __bfloat162float(h));
}

__global__ __launch_bounds__(256)
void split_rows(const float* __restrict__ in, __nv_bfloat16* __restrict__ hi,
                __nv_bfloat16* __restrict__ lo, int n4)
{
    int i = blockIdx.x * 256 + threadIdx.x;
    if (i >= n4) return;
    float4 v = ((const float4*)in)[i];
    __nv_bfloat16 h0, h1, h2, h3, l0, l1, l2, l3;
    split1(v.x, h0, l0); split1(v.y, h1, l1); split1(v.z, h2, l2); split1(v.w, h3, l3);
    __nv_bfloat162* hp = (__nv_bfloat162*)hi;
    __nv_bfloat162* lp = (__nv_bfloat162*)lo;
    hp[2 * i]     = __nv_bfloat162(h0, h1);
    hp[2 * i + 1] = __nv_bfloat162(h2, h3);
    lp[2 * i]     = __nv_bfloat162(l0, l1);
    lp[2 * i + 1] = __nv_bfloat162(l2, l3);
}

// W [K][N] fp32 -> B [N][K] bf16 hi/lo (transpose + split)
__global__ __launch_bounds__(256)
void split_transpose(const float* __restrict__ W, __nv_bfloat16* __restrict__ Bh,
                     __nv_bfloat16* __restrict__ Bl, int K, int N)
{
    __shared__ float ts[32][33];
    int n0 = blockIdx.x * 32, k0 = blockIdx.y * 32;
    int tx = threadIdx.x, ty = threadIdx.y;  // (32, 8)
#pragma unroll
    for (int i = 0; i < 4; i++)
        ts[ty + i * 8][tx] = W[(size_t)(k0 + ty + i * 8) * N + n0 + tx];
    __syncthreads();
#pragma unroll
    for (int i = 0; i < 4; i++) {
        float f = ts[tx][ty + i * 8];
        __nv_bfloat16 h, l;
        split1(f, h, l);
        size_t o = (size_t)(n0 + ty + i * 8) * K + k0 + tx;
        Bh[o] = h;
        Bl[o] = l;
    }
}

// ============================================================
// mma.sync split-bf16 GEMM. 128x128 CTA tile, BK=32, 8 warps,
// 3-stage cp.async, 2 CTAs/SM. Prefetch issued BEFORE compute.
// ============================================================
#define STAGE_BYTES 32768
#define GSTAGES 3
#define GSM_TOTAL (GSTAGES * STAGE_BYTES)

template<bool RES>
__global__ __launch_bounds__(256, 2)
void mma_gemm(const __nv_bfloat16* __restrict__ Ah, const __nv_bfloat16* __restrict__ Al,
              const __nv_bfloat16* __restrict__ Bh, const __nv_bfloat16* __restrict__ Bl,
              const float* __restrict__ bias, const float* __restrict__ res,
              float* __restrict__ C, int N, int K)
{
    extern __shared__ __align__(1024) char smem[];
    const uint32_t sb = smem_u32(smem);
    const int tid  = threadIdx.x;
    const int lane = tid & 31;
    const int warp = tid >> 5;
    const int wm = warp >> 2;
    const int wn = warp & 3;
    const int row0 = blockIdx.x * 128;
    const int col0 = blockIdx.y * 128;

    const int aRow = wm * 64 + (lane & 15);
    const uint32_t aSw = (uint32_t)((aRow >> 1) & 3);
    const uint32_t aCH = (uint32_t)(lane >> 4);
    const int bRow = wn * 32 + (((lane >> 4) & 1) << 3) + (lane & 7);
    const uint32_t bSw = (uint32_t)((bRow >> 1) & 3);
    const uint32_t bCH = (uint32_t)((lane >> 3) & 1);

    float acc[4][4][4];
#pragma unroll
    for (int mt = 0; mt < 4; mt++)
#pragma unroll
        for (int nt = 0; nt < 4; nt++)
#pragma unroll
            for (int e = 0; e < 4; e++) acc[mt][nt][e] = 0.f;

    const int ldRowA = row0 + (tid >> 2);
    const int ldRowB = col0 + (tid >> 2);
    const int ldC    = tid & 3;
    const uint32_t ldSw = ((uint32_t)(tid >> 2) * 64) ^
                          (((uint32_t)ldC ^ (((uint32_t)(tid >> 2) >> 1) & 3)) << 4);
    const uint32_t ldSw2 = (((uint32_t)(tid >> 2) + 64) * 64) ^
                           (((uint32_t)ldC ^ ((((uint32_t)(tid >> 2) + 64) >> 1) & 3)) << 4);

    const int NK = K / 32;

    auto load_stage = [&](int s, int k0) {
        uint32_t base = sb + (uint32_t)s * STAGE_BYTES;
        const __nv_bfloat16* gA0 = Ah + (size_t)ldRowA * K + k0 + ldC * 8;
        const __nv_bfloat16* gA1 = Al + (size_t)ldRowA * K + k0 + ldC * 8;
        const __nv_bfloat16* gB0 = Bh + (size_t)ldRowB * K + k0 + ldC * 8;
        const __nv_bfloat16* gB1 = Bl + (size_t)ldRowB * K + k0 + ldC * 8;
        const size_t off64 = (size_t)64 * K;
        cp_async16(base + ldSw,                gA0);
        cp_async16(base + ldSw2,               gA0 + off64);
        cp_async16(base + 8192  + ldSw,        gA1);
        cp_async16(base + 8192  + ldSw2,       gA1 + off64);
        cp_async16(base + 16384 + ldSw,        gB0);
        cp_async16(base + 16384 + ldSw2,       gB0 + off64);
        cp_async16(base + 24576 + ldSw,        gB1);
        cp_async16(base + 24576 + ldSw2,       gB1 + off64);
    };

    load_stage(0, 0);  cp_commit();
    load_stage(1, 32); cp_commit();

    int st = 0;
    for (int kt = 0; kt < NK; kt++) {
        cp_wait1();
        __syncthreads();

        // Prefetch stage kt+2 FIRST: its buffer was consumed at iter kt-1 and
        // all warps have passed this iteration's barrier, so it is free; the
        // loads now get a full iteration of compute to cover their latency.
        if (kt + 2 < NK) load_stage((st + 2) % GSTAGES, (kt + 2) * 32);
        cp_commit();

        uint32_t base = sb + (uint32_t)st * STAGE_BYTES;
        uint32_t aHiB = base +         (uint32_t)aRow * 64;
        uint32_t aLoB = aHiB + 8192;
        uint32_t bHiB = base + 16384 + (uint32_t)bRow * 64;
        uint32_t bLoB = bHiB + 8192;

#pragma unroll
        for (int k = 0; k < 2; k++) {
            const uint32_t ka = ((2u * k + aCH) ^ aSw) << 4;
            const uint32_t kb = ((2u * k + bCH) ^ bSw) << 4;
            uint32_t bhi[2][4], blo[2][4];
#pragma unroll
            for (int p = 0; p < 2; p++) {
                ldsm4(bhi[p], bHiB + p * 1024 + kb);
                ldsm4(blo[p], bLoB + p * 1024 + kb);
            }
#pragma unroll
            for (int mt = 0; mt < 4; mt++) {
                uint32_t ahi[4], alo[4];
                ldsm4(ahi, aHiB + mt * 1024 + ka);
                ldsm4(alo, aLoB + mt * 1024 + ka);
#pragma unroll
                for (int nt = 0; nt < 4; nt++) {
                    const uint32_t* bh2 = &bhi[nt >> 1][(nt & 1) * 2];
                    mma_bf16(acc[mt][nt], ahi, bh2);
                    mma_bf16(acc[mt][nt], ahi, &blo[nt >> 1][(nt & 1) * 2]);
                    mma_bf16(acc[mt][nt], alo, bh2);
                }
            }
        }
        st = (st + 1) % GSTAGES;
    }

    const int g  = lane >> 2;
    const int i4 = lane & 3;
#pragma unroll
    for (int mt = 0; mt < 4; mt++) {
        int r = row0 + wm * 64 + mt * 16 + g;
#pragma unroll
        for (int nt = 0; nt < 4; nt++) {
            int c = col0 + wn * 32 + nt * 8 + i4 * 2;
            float2 bv = *(const float2*)(bias + c);
            size_t o0 = (size_t)r * N + c;
            size_t o1 = (size_t)(r + 8) * N + c;
            float2 v0, v1;
            v0.x = acc[mt][nt][0] + bv.x; v0.y = acc[mt][nt][1] + bv.y;
            v1.x = acc[mt][nt][2] + bv.x; v1.y = acc[mt][nt][3] + bv.y;
            if (RES) {
                float2 r0 = *(const float2*)(res + o0);
                float2 r1 = *(const float2*)(res + o1);
                v0.x += r0.x; v0.y += r0.y;
                v1.x += r1.x; v1.y += r1.y;
            }
            *(float2*)(C + o0) = v0;
            *(float2*)(C + o1) = v1;
        }
    }
}

// ============================================================
// FA2-style attention on mma.sync, split-bf16 3-term.
// CTA: q-tile 128 (8 warps x m16), kv-tile 64. Per-batch launch.
// ============================================================
#define AQ_OFF   0u
#define AQL_OFF  32768u
#define AK_OFF   65536u
#define AKL_OFF  81920u
#define AV_OFF   98304u
#define AVL_OFF  114688u
#define AAL_OFF  131072u
#define ATTN_SMEM (131072 + 256)

__device__ __forceinline__ void store_split8(uint32_t baseH, uint32_t baseL,
                                             int r, int d, float4 v)
{
    uint32_t h01 = pack_bf16(v.x, v.y);
    uint32_t h23 = pack_bf16(v.z, v.w);
    float2 f01 = unpack_bf16(h01);
    float2 f23 = unpack_bf16(h23);
    uint32_t l01 = pack_bf16(v.x - f01.x, v.y - f01.y);
    uint32_t l23 = pack_bf16(v.z - f23.x, v.w - f23.y);
    uint32_t off = (uint32_t)r * 256 + ((((uint32_t)d >> 3) ^ ((uint32_t)r & 7)) << 4)
                 + (((uint32_t)d & 4) << 1);
    asm volatile("st.shared.v2.b32 [%0], {%1,%2};" :: "r"(baseH + off), "r"(h01), "r"(h23));
    asm volatile("st.shared.v2.b32 [%0], {%1,%2};" :: "r"(baseL + off), "r"(l01), "r"(l23));
}

__global__ __launch_bounds__(256, 1)
void attn_mma(const float* __restrict__ qkv, const float* __restrict__ alibi,
              __nv_bfloat16* __restrict__ Ch, __nv_bfloat16* __restrict__ Cl,
              int batch)
{
    extern __shared__ __align__(1024) char sm[];
    const uint32_t sb = smem_u32(sm);
    const uint32_t Qh = sb + AQ_OFF,  Ql = sb + AQL_OFF;
    const uint32_t Kh = sb + AK_OFF,  Kl = sb + AKL_OFF;
    const uint32_t Vh = sb + AV_OFF,  Vl = sb + AVL_OFF;
    float* al_s = (float*)(sm + AAL_OFF);

    const int qt   = (int)gridDim.x - 1 - (int)blockIdx.x;  // heavy tiles first
    const int h    = blockIdx.y;
    const int bh   = batch * 32 + h;
    const int tid  = threadIdx.x;
    const int lane = tid & 31;
    const int warp = tid >> 5;

    const size_t rowbase = (size_t)batch * S_;
    const int qcol = h * 384;
    const float* al = alibi + (size_t)bh * S_;
    const float inv = 0.08838834764831845f;

    // ---- load Q tile [128][128] fp32 -> split -> smem ----
#pragma unroll 4
    for (int it = 0; it < 16; it++) {
        int r = it * 8 + warp;
        int d = lane * 4;
        float4 v = *(const float4*)(qkv + (rowbase + qt * 128 + r) * NQKV_ + qcol + d);
        store_split8(Qh, Ql, r, d, v);
    }

    const int aRow = warp * 16 + (lane & 15);
    const uint32_t aChH = (uint32_t)(lane >> 4);
    const int bRowBase = (((lane >> 4) & 1) << 3) + (lane & 7);
    const uint32_t bChH = (uint32_t)((lane >> 3) & 1);
    const int vTok = (lane & 7) + (lane & 8);
    const int vD   = (lane >> 4) << 3;

    const int g  = lane >> 2;
    const int c2 = (lane & 3) * 2;
    const int qg0 = qt * 128 + warp * 16 + g;

    float O[16][4];
#pragma unroll
    for (int n = 0; n < 16; n++)
#pragma unroll
        for (int e = 0; e < 4; e++) O[n][e] = 0.f;
    float m0 = -1e30f, m1 = -1e30f, l0 = 0.f, l1 = 0.f;

    const int jmax = 2 * qt + 1;
    for (int j = 0; j <= jmax; j++) {
        __syncthreads();
#pragma unroll 4
        for (int it = 0; it < 8; it++) {
            int r = it * 8 + warp;
            int d = lane * 4;
            const float* src = qkv + (rowbase + j * 64 + r) * NQKV_ + qcol + d;
            float4 kv4 = *(const float4*)(src + 128);
            float4 vv4 = *(const float4*)(src + 256);
            store_split8(Kh, Kl, r, d, kv4);
            store_split8(Vh, Vl, r, d, vv4);
        }
        if (tid < 16) ((float4*)al_s)[tid] = *(const float4*)(al + j * 64 + tid * 4);
        __syncthreads();

        float S[8][4];
#pragma unroll
        for (int n = 0; n < 8; n++)
#pragma unroll
            for (int e = 0; e < 4; e++) S[n][e] = 0.f;

#pragma unroll
        for (int ks = 0; ks < 8; ks++) {
            uint32_t aOff = (uint32_t)aRow * 256 +
                (((2u * ks + aChH) ^ ((uint32_t)aRow & 7)) << 4);
            uint32_t ahi[4], alo[4];
            ldsm4(ahi, Qh + aOff);
            ldsm4(alo, Ql + aOff);
#pragma unroll
            for (int p = 0; p < 4; p++) {
                int bRow = p * 16 + bRowBase;
                uint32_t bOff = (uint32_t)bRow * 256 +
                    (((2u * ks + bChH) ^ ((uint32_t)bRow & 7)) << 4);
                uint32_t bhi[4], blo[4];
                ldsm4(bhi, Kh + bOff);
                ldsm4(blo, Kl + bOff);
#pragma unroll
                for (int q2 = 0; q2 < 2; q2++) {
                    int nt = p * 2 + q2;
                    mma_bf16(S[nt], ahi, &bhi[q2 * 2]);
                    mma_bf16(S[nt], ahi, &blo[q2 * 2]);
                    mma_bf16(S[nt], alo, &bhi[q2 * 2]);
                }
            }
        }

        const bool diag = (j * 64 + 63 > qt * 128 + warp * 16);
#pragma unroll
        for (int nt = 0; nt < 8; nt++) {
            float a0 = al_s[nt * 8 + c2];
            float a1 = al_s[nt * 8 + c2 + 1];
            S[nt][0] = S[nt][0] * inv + a0;
            S[nt][1] = S[nt][1] * inv + a1;
            S[nt][2] = S[nt][2] * inv + a0;
            S[nt][3] = S[nt][3] * inv + a1;
            if (diag) {
                int kg = j * 64 + nt * 8 + c2;
                if (kg     > qg0)     S[nt][0] = -1e30f;
                if (kg + 1 > qg0)     S[nt][1] = -1e30f;
                if (kg     > qg0 + 8) S[nt][2] = -1e30f;
                if (kg + 1 > qg0 + 8) S[nt][3] = -1e30f;
            }
        }

        float mx0 = -1e30f, mx1 = -1e30f;
#pragma unroll
        for (int nt = 0; nt < 8; nt++) {
            mx0 = fmaxf(mx0, fmaxf(S[nt][0], S[nt][1]));
            mx1 = fmaxf(mx1, fmaxf(S[nt][2], S[nt][3]));
        }
        mx0 = fmaxf(mx0, __shfl_xor_sync(0xffffffffu, mx0, 1));
        mx0 = fmaxf(mx0, __shfl_xor_sync(0xffffffffu, mx0, 2));
        mx1 = fmaxf(mx1, __shfl_xor_sync(0xffffffffu, mx1, 1));
        mx1 = fmaxf(mx1, __shfl_xor_sync(0xffffffffu, mx1, 2));
        float mn0 = fmaxf(m0, mx0), mn1 = fmaxf(m1, mx1);
        float sf0 = __expf(m0 - mn0), sf1 = __expf(m1 - mn1);
        float sum0 = 0.f, sum1 = 0.f;
#pragma unroll
        for (int nt = 0; nt < 8; nt++) {
            S[nt][0] = __expf(S[nt][0] - mn0); sum0 += S[nt][0];
            S[nt][1] = __expf(S[nt][1] - mn0); sum0 += S[nt][1];
            S[nt][2] = __expf(S[nt][2] - mn1); sum1 += S[nt][2];
            S[nt][3] = __expf(S[nt][3] - mn1); sum1 += S[nt][3];
        }
        sum0 += __shfl_xor_sync(0xffffffffu, sum0, 1);
        sum0 += __shfl_xor_sync(0xffffffffu, sum0, 2);
        sum1 += __shfl_xor_sync(0xffffffffu, sum1, 1);
        sum1 += __shfl_xor_sync(0xffffffffu, sum1, 2);
        l0 = l0 * sf0 + sum0; m0 = mn0;
        l1 = l1 * sf1 + sum1; m1 = mn1;
#pragma unroll
        for (int n = 0; n < 16; n++) {
            O[n][0] *= sf0; O[n][1] *= sf0;
            O[n][2] *= sf1; O[n][3] *= sf1;
        }

#pragma unroll
        for (int ks = 0; ks < 4; ks++) {
            uint32_t pa_hi[4], pa_lo[4];
            {
                float x0 = S[2 * ks][0],     x1 = S[2 * ks][1];
                float x2 = S[2 * ks][2],     x3 = S[2 * ks][3];
                float y0 = S[2 * ks + 1][0], y1 = S[2 * ks + 1][1];
                float y2 = S[2 * ks + 1][2], y3 = S[2 * ks + 1][3];
                pa_hi[0] = pack_bf16(x0, x1);
                pa_hi[1] = pack_bf16(x2, x3);
                pa_hi[2] = pack_bf16(y0, y1);
                pa_hi[3] = pack_bf16(y2, y3);
                float2 u;
                u = unpack_bf16(pa_hi[0]); pa_lo[0] = pack_bf16(x0 - u.x, x1 - u.y);
                u = unpack_bf16(pa_hi[1]); pa_lo[1] = pack_bf16(x2 - u.x, x3 - u.y);
                u = unpack_bf16(pa_hi[2]); pa_lo[2] = pack_bf16(y0 - u.x, y1 - u.y);
                u = unpack_bf16(pa_hi[3]); pa_lo[3] = pack_bf16(y2 - u.x, y3 - u.y);
            }
            int tok = ks * 16 + vTok;
            uint32_t tRow = (uint32_t)tok * 256;
            uint32_t tSw  = (uint32_t)tok & 7;
#pragma unroll
            for (int nt16 = 0; nt16 < 8; nt16++) {
                int d = nt16 * 16 + vD;
                uint32_t vOff = tRow + ((((uint32_t)d >> 3) ^ tSw) << 4);
                uint32_t bvh[4], bvl[4];
                ldsm4t(bvh, Vh + vOff);
                ldsm4t(bvl, Vl + vOff);
                mma_bf16(O[nt16 * 2],     pa_hi, &bvh[0]);
                mma_bf16(O[nt16 * 2 + 1], pa_hi, &bvh[2]);
                mma_bf16(O[nt16 * 2],     pa_hi, &bvl[0]);
                mma_bf16(O[nt16 * 2 + 1], pa_hi, &bvl[2]);
                mma_bf16(O[nt16 * 2],     pa_lo, &bvh[0]);
                mma_bf16(O[nt16 * 2 + 1], pa_lo, &bvh[2]);
            }
        }
    }

    float il0 = 1.f / l0, il1 = 1.f / l1;
    size_t r0 = rowbase + qt * 128 + warp * 16 + g;
    size_t r1 = r0 + 8;
#pragma unroll
    for (int n = 0; n < 16; n++) {
        int col = h * 128 + n * 8 + c2;
        float o00 = O[n][0] * il0, o01 = O[n][1] * il0;
        float o10 = O[n][2] * il1, o11 = O[n][3] * il1;
        uint32_t h0 = pack_bf16(o00, o01);
        uint32_t h1 = pack_bf16(o10, o11);
        float2 u0 = unpack_bf16(h0);
        float2 u1 = unpack_bf16(h1);
        uint32_t lo0 = pack_bf16(o00 - u0.x, o01 - u0.y);
        uint32_t lo1 = pack_bf16(o10 - u1.x, o11 - u1.y);
        *(uint32_t*)(Ch + r0 * H_ + col) = h0;
        *(uint32_t*)(Cl + r0 * H_ + col) = lo0;
        *(uint32_t*)(Ch + r1 * H_ + col) = h1;
        *(uint32_t*)(Cl + r1 * H_ + col) = lo1;
    }
}

// ============================================================
// Launch: 2-stream overlapped schedule (graph-capture safe
// fork/join via events). Stream s1 handles batch-1 chain and
// the Wd split; default stream handles batch-0 chain.
// ============================================================
extern "C" void kernel_launch(void* const* d_in, const int* in_sizes, int n_in,
                              void* d_out, int out_size)
{
    const float* hidden   = (const float*)d_in[0];
    const float* residual = (const float*)d_in[1];
    const float* alibi    = (const float*)d_in[2];
    const float* Wqkv     = (const float*)d_in[4];
    const float* bqkv     = (const float*)d_in[5];
    const float* Wd       = (const float*)d_in[6];
    const float* bd       = (const float*)d_in[7];
    float* out = (float*)d_out;

    void* p;
    cudaGetSymbolAddress(&p, g_qkv); float* qkv = (float*)p;
    cudaGetSymbolAddress(&p, g_Ah);  __nv_bfloat16* Ah  = (__nv_bfloat16*)p;
    cudaGetSymbolAddress(&p, g_Al);  __nv_bfloat16* Al  = (__nv_bfloat16*)p;
    cudaGetSymbolAddress(&p, g_Bqh); __nv_bfloat16* Bqh = (__nv_bfloat16*)p;
    cudaGetSymbolAddress(&p, g_Bql); __nv_bfloat16* Bql = (__nv_bfloat16*)p;
    cudaGetSymbolAddress(&p, g_Bdh); __nv_bfloat16* Bdh = (__nv_bfloat16*)p;
    cudaGetSymbolAddress(&p, g_Bdl); __nv_bfloat16* Bdl = (__nv_bfloat16*)p;
    cudaGetSymbolAddress(&p, g_Ch);  __nv_bfloat16* Ch  = (__nv_bfloat16*)p;
    cudaGetSymbolAddress(&p, g_Cl);  __nv_bfloat16* Cl  = (__nv_bfloat16*)p;

    cudaFuncSetAttribute(attn_mma, cudaFuncAttributeMaxDynamicSharedMemorySize, ATTN_SMEM);
    cudaFuncSetAttribute(mma_gemm<false>, cudaFuncAttributeMaxDynamicSharedMemorySize, GSM_TOTAL);
    cudaFuncSetAttribute(mma_gemm<true>,  cudaFuncAttributeMaxDynamicSharedMemorySize, GSM_TOTAL);

    cudaStream_t s1;
    cudaStreamCreateWithFlags(&s1, cudaStreamNonBlocking);
    cudaEvent_t ev0, evBd, evQ, evE;
    cudaEventCreateWithFlags(&ev0,  cudaEventDisableTiming);
    cudaEventCreateWithFlags(&evBd, cudaEventDisableTiming);
    cudaEventCreateWithFlags(&evQ,  cudaEventDisableTiming);
    cudaEventCreateWithFlags(&evE,  cudaEventDisableTiming);

    const size_t half = (size_t)S_ * H_;   // 1024 rows

    // fork s1 from the capture (default) stream
    cudaEventRecord(ev0, 0);
    cudaStreamWaitEvent(s1, ev0, 0);

    // s1: dense-weight split (only needed by the dense GEMMs)
    split_transpose<<<dim3(H_ / 32, H_ / 32), dim3(32, 8), 0, s1>>>(Wd, Bdh, Bdl, H_, H_);
    cudaEventRecord(evBd, s1);

    // default stream: activation + QKV-weight splits, then QKV projection
    split_rows<<<(M_ * H_ / 4 + 255) / 256, 256>>>(hidden, Ah, Al, M_ * H_ / 4);
    split_transpose<<<dim3(NQKV_ / 32, H_ / 32), dim3(32, 8)>>>(Wqkv, Bqh, Bql, H_, NQKV_);
    mma_gemm<false><<<dim3(M_ / 128, NQKV_ / 128), 256, GSM_TOTAL>>>(
        Ah, Al, Bqh, Bql, bqkv, nullptr, qkv, NQKV_, H_);
    cudaEventRecord(evQ, 0);

    // s1: batch-1 attention then batch-1 dense (s1 already has Bd split done)
    cudaStreamWaitEvent(s1, evQ, 0);
    attn_mma<<<dim3(8, 32), 256, ATTN_SMEM, s1>>>(qkv, alibi, Ch, Cl, 1);
    mma_gemm<true><<<dim3(8, H_ / 128), 256, GSM_TOTAL, s1>>>(
        Ch + half, Cl + half, Bdh, Bdl, bd, residual + half, out + half, H_, H_);
    cudaEventRecord(evE, s1);

    // default stream: batch-0 attention then batch-0 dense
    attn_mma<<<dim3(8, 32), 256, ATTN_SMEM>>>(qkv, alibi, Ch, Cl, 0);
    cudaStreamWaitEvent(0, evBd, 0);
    mma_gemm<true><<<dim3(8, H_ / 128), 256, GSM_TOTAL>>>(
        Ch, Cl, Bdh, Bdl, bd, residual, out, H_, H_);

    // join s1 back into the capture stream
    cudaStreamWaitEvent(0, evE, 0);
}

// round 8
// speedup vs baseline: 1.0710x; 1.0710x over previous
#include <cuda_runtime.h>
#include <cuda_bf16.h>
#include <stdint.h>
#include <math.h>

// Problem constants
#define B_    2
#define S_    1024
#define H_    4096
#define NH_   32
#define HD_   128
#define M_    2048
#define NQKV_ 12288

// ---------------- device scratch (no runtime allocation) ----------------
__device__ __nv_bfloat16 g_QKVh[(size_t)M_ * NQKV_];
__device__ __nv_bfloat16 g_QKVl[(size_t)M_ * NQKV_];
__device__ __nv_bfloat16 g_Ah[(size_t)M_ * H_];
__device__ __nv_bfloat16 g_Al[(size_t)M_ * H_];
__device__ __nv_bfloat16 g_Bqh[(size_t)NQKV_ * H_];
__device__ __nv_bfloat16 g_Bql[(size_t)NQKV_ * H_];
__device__ __nv_bfloat16 g_Bdh[(size_t)H_ * H_];
__device__ __nv_bfloat16 g_Bdl[(size_t)H_ * H_];
__device__ __nv_bfloat16 g_Ch[(size_t)M_ * H_];
__device__ __nv_bfloat16 g_Cl[(size_t)M_ * H_];

// ---------------- PTX helpers (portable, non-'a' features only) ----------------
__device__ __forceinline__ uint32_t smem_u32(const void* p) {
    uint32_t a;
    asm("{ .reg .u64 t; cvta.to.shared.u64 t, %1; cvt.u32.u64 %0, t; }" : "=r"(a) : "l"(p));
    return a;
}
__device__ __forceinline__ void cp_async16(uint32_t dst_smem, const void* src) {
    asm volatile("cp.async.cg.shared.global [%0], [%1], 16;"
                 :: "r"(dst_smem), "l"(src) : "memory");
}
__device__ __forceinline__ void cp_commit() {
    asm volatile("cp.async.commit_group;" ::: "memory");
}
__device__ __forceinline__ void cp_wait1() {
    asm volatile("cp.async.wait_group 1;" ::: "memory");
}
__device__ __forceinline__ void ldsm4(uint32_t* r, uint32_t addr) {
    asm volatile("ldmatrix.sync.aligned.m8n8.x4.shared.b16 {%0,%1,%2,%3}, [%4];"
                 : "=r"(r[0]), "=r"(r[1]), "=r"(r[2]), "=r"(r[3]) : "r"(addr));
}
__device__ __forceinline__ void ldsm4t(uint32_t* r, uint32_t addr) {
    asm volatile("ldmatrix.sync.aligned.m8n8.x4.trans.shared.b16 {%0,%1,%2,%3}, [%4];"
                 : "=r"(r[0]), "=r"(r[1]), "=r"(r[2]), "=r"(r[3]) : "r"(addr));
}
__device__ __forceinline__ void mma_bf16(float* d, const uint32_t* a, const uint32_t* b) {
    asm volatile(
        "mma.sync.aligned.m16n8k16.row.col.f32.bf16.bf16.f32 "
        "{%0,%1,%2,%3}, {%4,%5,%6,%7}, {%8,%9}, {%0,%1,%2,%3};"
        : "+f"(d[0]), "+f"(d[1]), "+f"(d[2]), "+f"(d[3])
        : "r"(a[0]), "r"(a[1]), "r"(a[2]), "r"(a[3]), "r"(b[0]), "r"(b[1]));
}
__device__ __forceinline__ uint32_t pack_bf16(float lo, float hi) {
    uint32_t r;
    asm("cvt.rn.bf16x2.f32 %0, %1, %2;" : "=r"(r) : "f"(hi), "f"(lo));
    return r;
}
__device__ __forceinline__ float2 unpack_bf16(uint32_t v) {
    __nv_bfloat162 h = *reinterpret_cast<__nv_bfloat162*>(&v);
    return __bfloat1622float2(h);
}

// ---------------- split helpers ----------------
__device__ __forceinline__ void split1(float f, __nv_bfloat16& h, __nv_bfloat16& l) {
    h = __float2bfloat16(f);
    l = __float2bfloat16(f - __bfloat162float(h));
}

__global__ __launch_bounds__(256)
void split_rows(const float* __restrict__ in, __nv_bfloat16* __restrict__ hi,
                __nv_bfloat16* __restrict__ lo, int n4)
{
    int i = blockIdx.x * 256 + threadIdx.x;
    if (i >= n4) return;
    float4 v = ((const float4*)in)[i];
    __nv_bfloat16 h0, h1, h2, h3, l0, l1, l2, l3;
    split1(v.x, h0, l0); split1(v.y, h1, l1); split1(v.z, h2, l2); split1(v.w, h3, l3);
    __nv_bfloat162* hp = (__nv_bfloat162*)hi;
    __nv_bfloat162* lp = (__nv_bfloat162*)lo;
    hp[2 * i]     = __nv_bfloat162(h0, h1);
    hp[2 * i + 1] = __nv_bfloat162(h2, h3);
    lp[2 * i]     = __nv_bfloat162(l0, l1);
    lp[2 * i + 1] = __nv_bfloat162(l2, l3);
}

// W [K][N] fp32 -> B [N][K] bf16 hi/lo (transpose + split)
__global__ __launch_bounds__(256)
void split_transpose(const float* __restrict__ W, __nv_bfloat16* __restrict__ Bh,
                     __nv_bfloat16* __restrict__ Bl, int K, int N)
{
    __shared__ float ts[32][33];
    int n0 = blockIdx.x * 32, k0 = blockIdx.y * 32;
    int tx = threadIdx.x, ty = threadIdx.y;  // (32, 8)
#pragma unroll
    for (int i = 0; i < 4; i++)
        ts[ty + i * 8][tx] = W[(size_t)(k0 + ty + i * 8) * N + n0 + tx];
    __syncthreads();
#pragma unroll
    for (int i = 0; i < 4; i++) {
        float f = ts[tx][ty + i * 8];
        __nv_bfloat16 h, l;
        split1(f, h, l);
        size_t o = (size_t)(n0 + ty + i * 8) * K + k0 + tx;
        Bh[o] = h;
        Bl[o] = l;
    }
}

// ============================================================
// mma.sync split-bf16 GEMM (round-6 proven mainloop).
// SPLIT=true: write bf16 hi/lo outputs (for QKV -> attention).
// SPLIT=false: write fp32 C (+residual) -- final dense GEMM.
// ============================================================
#define STAGE_BYTES 32768
#define GSTAGES 3
#define GSM_TOTAL (GSTAGES * STAGE_BYTES)

template<bool RES, bool SPLIT>
__global__ __launch_bounds__(256, 2)
void mma_gemm(const __nv_bfloat16* __restrict__ Ah, const __nv_bfloat16* __restrict__ Al,
              const __nv_bfloat16* __restrict__ Bh, const __nv_bfloat16* __restrict__ Bl,
              const float* __restrict__ bias, const float* __restrict__ res,
              float* __restrict__ C,
              __nv_bfloat16* __restrict__ Oh, __nv_bfloat16* __restrict__ Ol,
              int N, int K)
{
    extern __shared__ __align__(1024) char smem[];
    const uint32_t sb = smem_u32(smem);
    const int tid  = threadIdx.x;
    const int lane = tid & 31;
    const int warp = tid >> 5;
    const int wm = warp >> 2;
    const int wn = warp & 3;
    const int row0 = blockIdx.x * 128;
    const int col0 = blockIdx.y * 128;

    const int aRow = wm * 64 + (lane & 15);
    const uint32_t aSw = (uint32_t)((aRow >> 1) & 3);
    const uint32_t aCH = (uint32_t)(lane >> 4);
    const int bRow = wn * 32 + (((lane >> 4) & 1) << 3) + (lane & 7);
    const uint32_t bSw = (uint32_t)((bRow >> 1) & 3);
    const uint32_t bCH = (uint32_t)((lane >> 3) & 1);

    float acc[4][4][4];
#pragma unroll
    for (int mt = 0; mt < 4; mt++)
#pragma unroll
        for (int nt = 0; nt < 4; nt++)
#pragma unroll
            for (int e = 0; e < 4; e++) acc[mt][nt][e] = 0.f;

    const int ldRowA = row0 + (tid >> 2);
    const int ldRowB = col0 + (tid >> 2);
    const int ldC    = tid & 3;
    const uint32_t ldSw = ((uint32_t)(tid >> 2) * 64) ^
                          (((uint32_t)ldC ^ (((uint32_t)(tid >> 2) >> 1) & 3)) << 4);
    const uint32_t ldSw2 = (((uint32_t)(tid >> 2) + 64) * 64) ^
                           (((uint32_t)ldC ^ ((((uint32_t)(tid >> 2) + 64) >> 1) & 3)) << 4);

    const int NK = K / 32;

    auto load_stage = [&](int s, int k0) {
        uint32_t base = sb + (uint32_t)s * STAGE_BYTES;
        const __nv_bfloat16* gA0 = Ah + (size_t)ldRowA * K + k0 + ldC * 8;
        const __nv_bfloat16* gA1 = Al + (size_t)ldRowA * K + k0 + ldC * 8;
        const __nv_bfloat16* gB0 = Bh + (size_t)ldRowB * K + k0 + ldC * 8;
        const __nv_bfloat16* gB1 = Bl + (size_t)ldRowB * K + k0 + ldC * 8;
        const size_t off64 = (size_t)64 * K;
        cp_async16(base + ldSw,                gA0);
        cp_async16(base + ldSw2,               gA0 + off64);
        cp_async16(base + 8192  + ldSw,        gA1);
        cp_async16(base + 8192  + ldSw2,       gA1 + off64);
        cp_async16(base + 16384 + ldSw,        gB0);
        cp_async16(base + 16384 + ldSw2,       gB0 + off64);
        cp_async16(base + 24576 + ldSw,        gB1);
        cp_async16(base + 24576 + ldSw2,       gB1 + off64);
    };

    load_stage(0, 0);  cp_commit();
    load_stage(1, 32); cp_commit();

    int st = 0;
    for (int kt = 0; kt < NK; kt++) {
        cp_wait1();
        __syncthreads();

        uint32_t base = sb + (uint32_t)st * STAGE_BYTES;
        uint32_t aHiB = base +         (uint32_t)aRow * 64;
        uint32_t aLoB = aHiB + 8192;
        uint32_t bHiB = base + 16384 + (uint32_t)bRow * 64;
        uint32_t bLoB = bHiB + 8192;

#pragma unroll
        for (int k = 0; k < 2; k++) {
            const uint32_t ka = ((2u * k + aCH) ^ aSw) << 4;
            const uint32_t kb = ((2u * k + bCH) ^ bSw) << 4;
            uint32_t bhi[2][4], blo[2][4];
#pragma unroll
            for (int p = 0; p < 2; p++) {
                ldsm4(bhi[p], bHiB + p * 1024 + kb);
                ldsm4(blo[p], bLoB + p * 1024 + kb);
            }
#pragma unroll
            for (int mt = 0; mt < 4; mt++) {
                uint32_t ahi[4], alo[4];
                ldsm4(ahi, aHiB + mt * 1024 + ka);
                ldsm4(alo, aLoB + mt * 1024 + ka);
#pragma unroll
                for (int nt = 0; nt < 4; nt++) {
                    const uint32_t* bh2 = &bhi[nt >> 1][(nt & 1) * 2];
                    mma_bf16(acc[mt][nt], ahi, bh2);
                    mma_bf16(acc[mt][nt], ahi, &blo[nt >> 1][(nt & 1) * 2]);
                    mma_bf16(acc[mt][nt], alo, bh2);
                }
            }
        }

        if (kt + 2 < NK) load_stage((st + 2) % GSTAGES, (kt + 2) * 32);
        cp_commit();
        st = (st + 1) % GSTAGES;
    }

    const int g  = lane >> 2;
    const int i4 = lane & 3;
#pragma unroll
    for (int mt = 0; mt < 4; mt++) {
        int r = row0 + wm * 64 + mt * 16 + g;
#pragma unroll
        for (int nt = 0; nt < 4; nt++) {
            int c = col0 + wn * 32 + nt * 8 + i4 * 2;
            float2 bv = *(const float2*)(bias + c);
            size_t o0 = (size_t)r * N + c;
            size_t o1 = (size_t)(r + 8) * N + c;
            float v00 = acc[mt][nt][0] + bv.x, v01 = acc[mt][nt][1] + bv.y;
            float v10 = acc[mt][nt][2] + bv.x, v11 = acc[mt][nt][3] + bv.y;
            if (SPLIT) {
                uint32_t h0 = pack_bf16(v00, v01);
                uint32_t h1 = pack_bf16(v10, v11);
                float2 u0 = unpack_bf16(h0);
                float2 u1 = unpack_bf16(h1);
                uint32_t l0 = pack_bf16(v00 - u0.x, v01 - u0.y);
                uint32_t l1 = pack_bf16(v10 - u1.x, v11 - u1.y);
                *(uint32_t*)(Oh + o0) = h0;
                *(uint32_t*)(Ol + o0) = l0;
                *(uint32_t*)(Oh + o1) = h1;
                *(uint32_t*)(Ol + o1) = l1;
            } else {
                float2 v0, v1;
                v0.x = v00; v0.y = v01;
                v1.x = v10; v1.y = v11;
                if (RES) {
                    float2 r0 = *(const float2*)(res + o0);
                    float2 r1 = *(const float2*)(res + o1);
                    v0.x += r0.x; v0.y += r0.y;
                    v1.x += r1.x; v1.y += r1.y;
                }
                *(float2*)(C + o0) = v0;
                *(float2*)(C + o1) = v1;
            }
        }
    }
}

// ============================================================
// FA2-style attention, mma.sync split-bf16 3-term.
// Inputs pre-split bf16; Q + double-buffered K/V via cp.async.
// CTA: q-tile 128 (8 warps x m16), kv-tile 64. Per-batch.
// smem: Qh 32K | Ql 32K | stage{0,1}: Kh,Kl,Vh,Vl 16K each.
// ============================================================
#define AQH_OFF  0u
#define AQL_OFF  32768u
#define ASTG_OFF 65536u
#define ASTG_SZ  65536u
#define ATTN_SMEM (65536 + 2 * 65536)   // 196608 B

__global__ __launch_bounds__(256, 1)
void attn_mma(const __nv_bfloat16* __restrict__ QKVh,
              const __nv_bfloat16* __restrict__ QKVl,
              const float* __restrict__ alibi,
              __nv_bfloat16* __restrict__ Ch, __nv_bfloat16* __restrict__ Cl,
              int batch)
{
    extern __shared__ __align__(1024) char sm[];
    const uint32_t sb = smem_u32(sm);
    const uint32_t Qh = sb + AQH_OFF, Ql = sb + AQL_OFF;

    const int qt   = (int)gridDim.x - 1 - (int)blockIdx.x;  // heavy tiles first
    const int h    = blockIdx.y;
    const int bh   = batch * 32 + h;
    const int tid  = threadIdx.x;
    const int lane = tid & 31;
    const int warp = tid >> 5;

    const size_t rowbase = (size_t)batch * S_;
    const int qcol = h * 384;
    const float* al = alibi + (size_t)bh * S_;
    const float inv = 0.08838834764831845f;

    // per-thread chunk map for async loads
    const int ldR = tid >> 4;          // 0..15
    const int ldCk = tid & 15;         // chunk 0..15

    auto load_q = [&]() {
#pragma unroll
        for (int i = 0; i < 8; i++) {
            int r = i * 16 + ldR;      // 0..127
            uint32_t dst = (uint32_t)r * 256 +
                (((uint32_t)ldCk ^ ((uint32_t)r & 7)) << 4);
            size_t goff = (rowbase + qt * 128 + r) * NQKV_ + qcol + ldCk * 8;
            cp_async16(Qh + dst, QKVh + goff);
            cp_async16(Ql + dst, QKVl + goff);
        }
    };
    auto load_kv = [&](int j, int slot) {
        uint32_t stg = sb + ASTG_OFF + (uint32_t)slot * ASTG_SZ;
#pragma unroll
        for (int i = 0; i < 4; i++) {
            int r = i * 16 + ldR;      // 0..63
            uint32_t dst = (uint32_t)r * 256 +
                (((uint32_t)ldCk ^ ((uint32_t)r & 7)) << 4);
            size_t goff = (rowbase + j * 64 + r) * NQKV_ + qcol + ldCk * 8;
            cp_async16(stg +         dst, QKVh + goff + 128);   // Khi
            cp_async16(stg + 16384 + dst, QKVl + goff + 128);   // Klo
            cp_async16(stg + 32768 + dst, QKVh + goff + 256);   // Vhi
            cp_async16(stg + 49152 + dst, QKVl + goff + 256);   // Vlo
        }
    };

    const int jmax = 2 * qt + 1;
    load_q(); load_kv(0, 0); cp_commit();
    if (jmax >= 1) load_kv(1, 1);
    cp_commit();

    const int aRow = warp * 16 + (lane & 15);
    const uint32_t aChH = (uint32_t)(lane >> 4);
    const int bRowBase = (((lane >> 4) & 1) << 3) + (lane & 7);
    const uint32_t bChH = (uint32_t)((lane >> 3) & 1);
    const int vTok = (lane & 7) + (lane & 8);
    const int vD   = (lane >> 4) << 3;

    const int g  = lane >> 2;
    const int c2 = (lane & 3) * 2;
    const int qg0 = qt * 128 + warp * 16 + g;

    float O[16][4];
#pragma unroll
    for (int n = 0; n < 16; n++)
#pragma unroll
        for (int e = 0; e < 4; e++) O[n][e] = 0.f;
    float m0 = -1e30f, m1 = -1e30f, l0 = 0.f, l1 = 0.f;

    for (int j = 0; j <= jmax; j++) {
        cp_wait1();
        __syncthreads();

        uint32_t stg = sb + ASTG_OFF + (uint32_t)(j & 1) * ASTG_SZ;
        const uint32_t Kh = stg, Kl = stg + 16384;
        const uint32_t Vh = stg + 32768, Vl = stg + 49152;

        float S[8][4];
#pragma unroll
        for (int n = 0; n < 8; n++)
#pragma unroll
            for (int e = 0; e < 4; e++) S[n][e] = 0.f;

#pragma unroll
        for (int ks = 0; ks < 8; ks++) {
            uint32_t aOff = (uint32_t)aRow * 256 +
                (((2u * ks + aChH) ^ ((uint32_t)aRow & 7)) << 4);
            uint32_t ahi[4], alo[4];
            ldsm4(ahi, Qh + aOff);
            ldsm4(alo, Ql + aOff);
#pragma unroll
            for (int p = 0; p < 4; p++) {
                int bRow = p * 16 + bRowBase;
                uint32_t bOff = (uint32_t)bRow * 256 +
                    (((2u * ks + bChH) ^ ((uint32_t)bRow & 7)) << 4);
                uint32_t bhi[4], blo[4];
                ldsm4(bhi, Kh + bOff);
                ldsm4(blo, Kl + bOff);
#pragma unroll
                for (int q2 = 0; q2 < 2; q2++) {
                    int nt = p * 2 + q2;
                    mma_bf16(S[nt], ahi, &bhi[q2 * 2]);
                    mma_bf16(S[nt], ahi, &blo[q2 * 2]);
                    mma_bf16(S[nt], alo, &bhi[q2 * 2]);
                }
            }
        }

        const bool diag = (j * 64 + 63 > qt * 128 + warp * 16);
#pragma unroll
        for (int nt = 0; nt < 8; nt++) {
            float2 a = *(const float2*)(al + j * 64 + nt * 8 + c2);
            S[nt][0] = S[nt][0] * inv + a.x;
            S[nt][1] = S[nt][1] * inv + a.y;
            S[nt][2] = S[nt][2] * inv + a.x;
            S[nt][3] = S[nt][3] * inv + a.y;
            if (diag) {
                int kg = j * 64 + nt * 8 + c2;
                if (kg     > qg0)     S[nt][0] = -1e30f;
                if (kg + 1 > qg0)     S[nt][1] = -1e30f;
                if (kg     > qg0 + 8) S[nt][2] = -1e30f;
                if (kg + 1 > qg0 + 8) S[nt][3] = -1e30f;
            }
        }

        float mx0 = -1e30f, mx1 = -1e30f;
#pragma unroll
        for (int nt = 0; nt < 8; nt++) {
            mx0 = fmaxf(mx0, fmaxf(S[nt][0], S[nt][1]));
            mx1 = fmaxf(mx1, fmaxf(S[nt][2], S[nt][3]));
        }
        mx0 = fmaxf(mx0, __shfl_xor_sync(0xffffffffu, mx0, 1));
        mx0 = fmaxf(mx0, __shfl_xor_sync(0xffffffffu, mx0, 2));
        mx1 = fmaxf(mx1, __shfl_xor_sync(0xffffffffu, mx1, 1));
        mx1 = fmaxf(mx1, __shfl_xor_sync(0xffffffffu, mx1, 2));
        float mn0 = fmaxf(m0, mx0), mn1 = fmaxf(m1, mx1);
        float sf0 = __expf(m0 - mn0), sf1 = __expf(m1 - mn1);
        float sum0 = 0.f, sum1 = 0.f;
#pragma unroll
        for (int nt = 0; nt < 8; nt++) {
            S[nt][0] = __expf(S[nt][0] - mn0); sum0 += S[nt][0];
            S[nt][1] = __expf(S[nt][1] - mn0); sum0 += S[nt][1];
            S[nt][2] = __expf(S[nt][2] - mn1); sum1 += S[nt][2];
            S[nt][3] = __expf(S[nt][3] - mn1); sum1 += S[nt][3];
        }
        sum0 += __shfl_xor_sync(0xffffffffu, sum0, 1);
        sum0 += __shfl_xor_sync(0xffffffffu, sum0, 2);
        sum1 += __shfl_xor_sync(0xffffffffu, sum1, 1);
        sum1 += __shfl_xor_sync(0xffffffffu, sum1, 2);
        l0 = l0 * sf0 + sum0; m0 = mn0;
        l1 = l1 * sf1 + sum1; m1 = mn1;
#pragma unroll
        for (int n = 0; n < 16; n++) {
            O[n][0] *= sf0; O[n][1] *= sf0;
            O[n][2] *= sf1; O[n][3] *= sf1;
        }

#pragma unroll
        for (int ks = 0; ks < 4; ks++) {
            uint32_t pa_hi[4], pa_lo[4];
            {
                float x0 = S[2 * ks][0],     x1 = S[2 * ks][1];
                float x2 = S[2 * ks][2],     x3 = S[2 * ks][3];
                float y0 = S[2 * ks + 1][0], y1 = S[2 * ks + 1][1];
                float y2 = S[2 * ks + 1][2], y3 = S[2 * ks + 1][3];
                pa_hi[0] = pack_bf16(x0, x1);
                pa_hi[1] = pack_bf16(x2, x3);
                pa_hi[2] = pack_bf16(y0, y1);
                pa_hi[3] = pack_bf16(y2, y3);
                float2 u;
                u = unpack_bf16(pa_hi[0]); pa_lo[0] = pack_bf16(x0 - u.x, x1 - u.y);
                u = unpack_bf16(pa_hi[1]); pa_lo[1] = pack_bf16(x2 - u.x, x3 - u.y);
                u = unpack_bf16(pa_hi[2]); pa_lo[2] = pack_bf16(y0 - u.x, y1 - u.y);
                u = unpack_bf16(pa_hi[3]); pa_lo[3] = pack_bf16(y2 - u.x, y3 - u.y);
            }
            int tok = ks * 16 + vTok;
            uint32_t tRow = (uint32_t)tok * 256;
            uint32_t tSw  = (uint32_t)tok & 7;
#pragma unroll
            for (int nt16 = 0; nt16 < 8; nt16++) {
                int d = nt16 * 16 + vD;
                uint32_t vOff = tRow + ((((uint32_t)d >> 3) ^ tSw) << 4);
                uint32_t bvh[4], bvl[4];
                ldsm4t(bvh, Vh + vOff);
                ldsm4t(bvl, Vl + vOff);
                mma_bf16(O[nt16 * 2],     pa_hi, &bvh[0]);
                mma_bf16(O[nt16 * 2 + 1], pa_hi, &bvh[2]);
                mma_bf16(O[nt16 * 2],     pa_hi, &bvl[0]);
                mma_bf16(O[nt16 * 2 + 1], pa_hi, &bvl[2]);
                mma_bf16(O[nt16 * 2],     pa_lo, &bvh[0]);
                mma_bf16(O[nt16 * 2 + 1], pa_lo, &bvh[2]);
            }
        }

        __syncthreads();   // all warps done with slot (j&1)
        if (j + 2 <= jmax) load_kv(j + 2, j & 1);
        cp_commit();
    }

    float il0 = 1.f / l0, il1 = 1.f / l1;
    size_t r0 = rowbase + qt * 128 + warp * 16 + g;
    size_t r1 = r0 + 8;
#pragma unroll
    for (int n = 0; n < 16; n++) {
        int col = h * 128 + n * 8 + c2;
        float o00 = O[n][0] * il0, o01 = O[n][1] * il0;
        float o10 = O[n][2] * il1, o11 = O[n][3] * il1;
        uint32_t h0 = pack_bf16(o00, o01);
        uint32_t h1 = pack_bf16(o10, o11);
        float2 u0 = unpack_bf16(h0);
        float2 u1 = unpack_bf16(h1);
        uint32_t lo0 = pack_bf16(o00 - u0.x, o01 - u0.y);
        uint32_t lo1 = pack_bf16(o10 - u1.x, o11 - u1.y);
        *(uint32_t*)(Ch + r0 * H_ + col) = h0;
        *(uint32_t*)(Cl + r0 * H_ + col) = lo0;
        *(uint32_t*)(Ch + r1 * H_ + col) = h1;
        *(uint32_t*)(Cl + r1 * H_ + col) = lo1;
    }
}

// ============================================================
// Launch: serial splits + QKV (no interference), then b0/b1
// attention+dense overlap via fork/join events.
// ============================================================
extern "C" void kernel_launch(void* const* d_in, const int* in_sizes, int n_in,
                              void* d_out, int out_size)
{
    const float* hidden   = (const float*)d_in[0];
    const float* residual = (const float*)d_in[1];
    const float* alibi    = (const float*)d_in[2];
    const float* Wqkv     = (const float*)d_in[4];
    const float* bqkv     = (const float*)d_in[5];
    const float* Wd       = (const float*)d_in[6];
    const float* bd       = (const float*)d_in[7];
    float* out = (float*)d_out;

    void* p;
    cudaGetSymbolAddress(&p, g_QKVh); __nv_bfloat16* QKVh = (__nv_bfloat16*)p;
    cudaGetSymbolAddress(&p, g_QKVl); __nv_bfloat16* QKVl = (__nv_bfloat16*)p;
    cudaGetSymbolAddress(&p, g_Ah);   __nv_bfloat16* Ah   = (__nv_bfloat16*)p;
    cudaGetSymbolAddress(&p, g_Al);   __nv_bfloat16* Al   = (__nv_bfloat16*)p;
    cudaGetSymbolAddress(&p, g_Bqh);  __nv_bfloat16* Bqh  = (__nv_bfloat16*)p;
    cudaGetSymbolAddress(&p, g_Bql);  __nv_bfloat16* Bql  = (__nv_bfloat16*)p;
    cudaGetSymbolAddress(&p, g_Bdh);  __nv_bfloat16* Bdh  = (__nv_bfloat16*)p;
    cudaGetSymbolAddress(&p, g_Bdl);  __nv_bfloat16* Bdl  = (__nv_bfloat16*)p;
    cudaGetSymbolAddress(&p, g_Ch);   __nv_bfloat16* Ch   = (__nv_bfloat16*)p;
    cudaGetSymbolAddress(&p, g_Cl);   __nv_bfloat16* Cl   = (__nv_bfloat16*)p;

    cudaFuncSetAttribute(attn_mma, cudaFuncAttributeMaxDynamicSharedMemorySize, ATTN_SMEM);
    cudaFuncSetAttribute(mma_gemm<false, true>,
                         cudaFuncAttributeMaxDynamicSharedMemorySize, GSM_TOTAL);
    cudaFuncSetAttribute(mma_gemm<true, false>,
                         cudaFuncAttributeMaxDynamicSharedMemorySize, GSM_TOTAL);

    cudaStream_t s1;
    cudaStreamCreateWithFlags(&s1, cudaStreamNonBlocking);
    cudaEvent_t evQ, evE;
    cudaEventCreateWithFlags(&evQ, cudaEventDisableTiming);
    cudaEventCreateWithFlags(&evE, cudaEventDisableTiming);

    const size_t half = (size_t)S_ * H_;   // 1024 rows

    // serial: splits then QKV projection (split bf16 output)
    split_rows<<<(M_ * H_ / 4 + 255) / 256, 256>>>(hidden, Ah, Al, M_ * H_ / 4);
    split_transpose<<<dim3(NQKV_ / 32, H_ / 32), dim3(32, 8)>>>(Wqkv, Bqh, Bql, H_, NQKV_);
    split_transpose<<<dim3(H_ / 32, H_ / 32), dim3(32, 8)>>>(Wd, Bdh, Bdl, H_, H_);
    mma_gemm<false, true><<<dim3(M_ / 128, NQKV_ / 128), 256, GSM_TOTAL>>>(
        Ah, Al, Bqh, Bql, bqkv, nullptr, nullptr, QKVh, QKVl, NQKV_, H_);
    cudaEventRecord(evQ, 0);

    // s1: batch-1 attention then batch-1 dense
    cudaStreamWaitEvent(s1, evQ, 0);
    attn_mma<<<dim3(8, 32), 256, ATTN_SMEM, s1>>>(QKVh, QKVl, alibi, Ch, Cl, 1);
    mma_gemm<true, false><<<dim3(8, H_ / 128), 256, GSM_TOTAL, s1>>>(
        Ch + half, Cl + half, Bdh, Bdl, bd, residual + half, out + half,
        nullptr, nullptr, H_, H_);
    cudaEventRecord(evE, s1);

    // main: batch-0 attention then batch-0 dense
    attn_mma<<<dim3(8, 32), 256, ATTN_SMEM>>>(QKVh, QKVl, alibi, Ch, Cl, 0);
    mma_gemm<true, false><<<dim3(8, H_ / 128), 256, GSM_TOTAL>>>(
        Ch, Cl, Bdh, Bdl, bd, residual, out, nullptr, nullptr, H_, H_);

    // join
    cudaStreamWaitEvent(0, evE, 0);
}

// round 9
// speedup vs baseline: 1.4270x; 1.3324x over previous
#include <cuda_runtime.h>
#include <cuda_fp16.h>
#include <stdint.h>
#include <math.h>

// Problem constants
#define B_    2
#define S_    1024
#define H_    4096
#define NH_   32
#define HD_   128
#define M_    2048
#define NQKV_ 12288

// ---------------- device scratch (no runtime allocation) ----------------
__device__ __half g_QKVh[(size_t)M_ * NQKV_];
__device__ __half g_QKVl[(size_t)M_ * NQKV_];
__device__ __half g_Ah[(size_t)M_ * H_];
__device__ __half g_Bqh[(size_t)NQKV_ * H_];
__device__ __half g_Bql[(size_t)NQKV_ * H_];
__device__ __half g_Bdh[(size_t)H_ * H_];
__device__ __half g_Bdl[(size_t)H_ * H_];
__device__ __half g_Ch[(size_t)M_ * H_];

// ---------------- PTX helpers (portable, non-'a' features only) ----------------
__device__ __forceinline__ uint32_t smem_u32(const void* p) {
    uint32_t a;
    asm("{ .reg .u64 t; cvta.to.shared.u64 t, %1; cvt.u32.u64 %0, t; }" : "=r"(a) : "l"(p));
    return a;
}
__device__ __forceinline__ void cp_async16(uint32_t dst_smem, const void* src) {
    asm volatile("cp.async.cg.shared.global [%0], [%1], 16;"
                 :: "r"(dst_smem), "l"(src) : "memory");
}
__device__ __forceinline__ void cp_commit() {
    asm volatile("cp.async.commit_group;" ::: "memory");
}
__device__ __forceinline__ void cp_wait1() {
    asm volatile("cp.async.wait_group 1;" ::: "memory");
}
__device__ __forceinline__ void ldsm4(uint32_t* r, uint32_t addr) {
    asm volatile("ldmatrix.sync.aligned.m8n8.x4.shared.b16 {%0,%1,%2,%3}, [%4];"
                 : "=r"(r[0]), "=r"(r[1]), "=r"(r[2]), "=r"(r[3]) : "r"(addr));
}
__device__ __forceinline__ void ldsm4t(uint32_t* r, uint32_t addr) {
    asm volatile("ldmatrix.sync.aligned.m8n8.x4.trans.shared.b16 {%0,%1,%2,%3}, [%4];"
                 : "=r"(r[0]), "=r"(r[1]), "=r"(r[2]), "=r"(r[3]) : "r"(addr));
}
__device__ __forceinline__ void mma_f16(float* d, const uint32_t* a, const uint32_t* b) {
    asm volatile(
        "mma.sync.aligned.m16n8k16.row.col.f32.f16.f16.f32 "
        "{%0,%1,%2,%3}, {%4,%5,%6,%7}, {%8,%9}, {%0,%1,%2,%3};"
        : "+f"(d[0]), "+f"(d[1]), "+f"(d[2]), "+f"(d[3])
        : "r"(a[0]), "r"(a[1]), "r"(a[2]), "r"(a[3]), "r"(b[0]), "r"(b[1]));
}
// pack two floats to f16x2: low half = lo, high half = hi
__device__ __forceinline__ uint32_t pack_f16(float lo, float hi) {
    uint32_t r;
    asm("cvt.rn.f16x2.f32 %0, %1, %2;" : "=r"(r) : "f"(hi), "f"(lo));
    return r;
}
__device__ __forceinline__ float2 unpack_f16(uint32_t v) {
    __half2 h = *reinterpret_cast<__half2*>(&v);
    return __half22float2(h);
}

// ---------------- split helpers ----------------
__device__ __forceinline__ void split1h(float f, __half& h, __half& l) {
    h = __float2half_rn(f);
    l = __float2half_rn(f - __half2float(h));
}

// fp32 -> single f16 (A-side operands)
__global__ __launch_bounds__(256)
void conv_rows(const float* __restrict__ in, __half* __restrict__ hi, int n4)
{
    int i = blockIdx.x * 256 + threadIdx.x;
    if (i >= n4) return;
    float4 v = ((const float4*)in)[i];
    uint32_t* hp = (uint32_t*)hi;
    hp[2 * i]     = pack_f16(v.x, v.y);
    hp[2 * i + 1] = pack_f16(v.z, v.w);
}

// W [K][N] fp32 -> B [N][K] f16 hi/lo (transpose + split)
__global__ __launch_bounds__(256)
void split_transpose(const float* __restrict__ W, __half* __restrict__ Bh,
                     __half* __restrict__ Bl, int K, int N)
{
    __shared__ float ts[32][33];
    int n0 = blockIdx.x * 32, k0 = blockIdx.y * 32;
    int tx = threadIdx.x, ty = threadIdx.y;  // (32, 8)
#pragma unroll
    for (int i = 0; i < 4; i++)
        ts[ty + i * 8][tx] = W[(size_t)(k0 + ty + i * 8) * N + n0 + tx];
    __syncthreads();
#pragma unroll
    for (int i = 0; i < 4; i++) {
        float f = ts[tx][ty + i * 8];
        __half h, l;
        split1h(f, h, l);
        size_t o = (size_t)(n0 + ty + i * 8) * K + k0 + tx;
        Bh[o] = h;
        Bl[o] = l;
    }
}

// ============================================================
// mma.sync 2-term f16 GEMM: C = A(f16) @ (Bhi+Blo)^T + bias.
// 128x128 CTA tile, BK=32, 8 warps, 3-stage cp.async, 2 CTA/SM.
// Stage: A 8KB | Bh 8KB | Bl 8KB = 24KB.
// SPLIT=true: write f16 hi/lo outputs. Else fp32 (+residual).
// ============================================================
#define STAGE_BYTES 24576
#define GSTAGES 3
#define GSM_TOTAL (GSTAGES * STAGE_BYTES)   // 73728

template<bool RES, bool SPLIT>
__global__ __launch_bounds__(256, 2)
void mma_gemm(const __half* __restrict__ A,
              const __half* __restrict__ Bh, const __half* __restrict__ Bl,
              const float* __restrict__ bias, const float* __restrict__ res,
              float* __restrict__ C,
              __half* __restrict__ Oh, __half* __restrict__ Ol,
              int N, int K)
{
    extern __shared__ __align__(1024) char smem[];
    const uint32_t sb = smem_u32(smem);
    const int tid  = threadIdx.x;
    const int lane = tid & 31;
    const int warp = tid >> 5;
    const int wm = warp >> 2;
    const int wn = warp & 3;
    const int row0 = blockIdx.x * 128;
    const int col0 = blockIdx.y * 128;

    const int aRow = wm * 64 + (lane & 15);
    const uint32_t aSw = (uint32_t)((aRow >> 1) & 3);
    const uint32_t aCH = (uint32_t)(lane >> 4);
    const int bRow = wn * 32 + (((lane >> 4) & 1) << 3) + (lane & 7);
    const uint32_t bSw = (uint32_t)((bRow >> 1) & 3);
    const uint32_t bCH = (uint32_t)((lane >> 3) & 1);

    float acc[4][4][4];
#pragma unroll
    for (int mt = 0; mt < 4; mt++)
#pragma unroll
        for (int nt = 0; nt < 4; nt++)
#pragma unroll
            for (int e = 0; e < 4; e++) acc[mt][nt][e] = 0.f;

    const int ldRowA = row0 + (tid >> 2);
    const int ldRowB = col0 + (tid >> 2);
    const int ldC    = tid & 3;
    const uint32_t ldSw = ((uint32_t)(tid >> 2) * 64) ^
                          (((uint32_t)ldC ^ (((uint32_t)(tid >> 2) >> 1) & 3)) << 4);
    const uint32_t ldSw2 = (((uint32_t)(tid >> 2) + 64) * 64) ^
                           (((uint32_t)ldC ^ ((((uint32_t)(tid >> 2) + 64) >> 1) & 3)) << 4);

    const int NK = K / 32;

    auto load_stage = [&](int s, int k0) {
        uint32_t base = sb + (uint32_t)s * STAGE_BYTES;
        const __half* gA  = A  + (size_t)ldRowA * K + k0 + ldC * 8;
        const __half* gB0 = Bh + (size_t)ldRowB * K + k0 + ldC * 8;
        const __half* gB1 = Bl + (size_t)ldRowB * K + k0 + ldC * 8;
        const size_t off64 = (size_t)64 * K;
        cp_async16(base + ldSw,           gA);
        cp_async16(base + ldSw2,          gA + off64);
        cp_async16(base + 8192  + ldSw,   gB0);
        cp_async16(base + 8192  + ldSw2,  gB0 + off64);
        cp_async16(base + 16384 + ldSw,   gB1);
        cp_async16(base + 16384 + ldSw2,  gB1 + off64);
    };

    load_stage(0, 0);  cp_commit();
    load_stage(1, 32); cp_commit();

    int st = 0;
    for (int kt = 0; kt < NK; kt++) {
        cp_wait1();
        __syncthreads();

        uint32_t base = sb + (uint32_t)st * STAGE_BYTES;
        uint32_t aB   = base +         (uint32_t)aRow * 64;
        uint32_t bHiB = base + 8192  + (uint32_t)bRow * 64;
        uint32_t bLoB = base + 16384 + (uint32_t)bRow * 64;

#pragma unroll
        for (int k = 0; k < 2; k++) {
            const uint32_t ka = ((2u * k + aCH) ^ aSw) << 4;
            const uint32_t kb = ((2u * k + bCH) ^ bSw) << 4;
            uint32_t bhi[2][4], blo[2][4];
#pragma unroll
            for (int p = 0; p < 2; p++) {
                ldsm4(bhi[p], bHiB + p * 1024 + kb);
                ldsm4(blo[p], bLoB + p * 1024 + kb);
            }
#pragma unroll
            for (int mt = 0; mt < 4; mt++) {
                uint32_t av[4];
                ldsm4(av, aB + mt * 1024 + ka);
#pragma unroll
                for (int nt = 0; nt < 4; nt++) {
                    mma_f16(acc[mt][nt], av, &bhi[nt >> 1][(nt & 1) * 2]);
                    mma_f16(acc[mt][nt], av, &blo[nt >> 1][(nt & 1) * 2]);
                }
            }
        }

        if (kt + 2 < NK) load_stage((st + 2) % GSTAGES, (kt + 2) * 32);
        cp_commit();
        st = (st + 1) % GSTAGES;
    }

    const int g  = lane >> 2;
    const int i4 = lane & 3;
#pragma unroll
    for (int mt = 0; mt < 4; mt++) {
        int r = row0 + wm * 64 + mt * 16 + g;
#pragma unroll
        for (int nt = 0; nt < 4; nt++) {
            int c = col0 + wn * 32 + nt * 8 + i4 * 2;
            float2 bv = *(const float2*)(bias + c);
            size_t o0 = (size_t)r * N + c;
            size_t o1 = (size_t)(r + 8) * N + c;
            float v00 = acc[mt][nt][0] + bv.x, v01 = acc[mt][nt][1] + bv.y;
            float v10 = acc[mt][nt][2] + bv.x, v11 = acc[mt][nt][3] + bv.y;
            if (SPLIT) {
                uint32_t h0 = pack_f16(v00, v01);
                uint32_t h1 = pack_f16(v10, v11);
                float2 u0 = unpack_f16(h0);
                float2 u1 = unpack_f16(h1);
                uint32_t l0 = pack_f16(v00 - u0.x, v01 - u0.y);
                uint32_t l1 = pack_f16(v10 - u1.x, v11 - u1.y);
                *(uint32_t*)(Oh + o0) = h0;
                *(uint32_t*)(Ol + o0) = l0;
                *(uint32_t*)(Oh + o1) = h1;
                *(uint32_t*)(Ol + o1) = l1;
            } else {
                float2 v0, v1;
                v0.x = v00; v0.y = v01;
                v1.x = v10; v1.y = v11;
                if (RES) {
                    float2 r0 = *(const float2*)(res + o0);
                    float2 r1 = *(const float2*)(res + o1);
                    v0.x += r0.x; v0.y += r0.y;
                    v1.x += r1.x; v1.y += r1.y;
                }
                *(float2*)(C + o0) = v0;
                *(float2*)(C + o1) = v1;
            }
        }
    }
}

// ============================================================
// FA2-style attention, mma.sync 2-term f16.
// Q single f16; K,V split hi/lo (pre-split by QKV epilogue).
// CTA: q-tile 128 (8 warps x m16), kv-tile 64, double-buffered.
// smem: Q 32K | stage{0,1}: Kh,Kl,Vh,Vl 16K each = 64K/stage.
// ============================================================
#define AQ_OFF   0u
#define ASTG_OFF 32768u
#define ASTG_SZ  65536u
#define ATTN_SMEM (32768 + 2 * 65536)   // 163840 B

__global__ __launch_bounds__(256, 1)
void attn_mma(const __half* __restrict__ QKVh,
              const __half* __restrict__ QKVl,
              const float* __restrict__ alibi,
              __half* __restrict__ Ch, int batch)
{
    extern __shared__ __align__(1024) char sm[];
    const uint32_t sb = smem_u32(sm);
    const uint32_t Qs = sb + AQ_OFF;

    const int qt   = (int)gridDim.x - 1 - (int)blockIdx.x;  // heavy tiles first
    const int h    = blockIdx.y;
    const int bh   = batch * 32 + h;
    const int tid  = threadIdx.x;
    const int lane = tid & 31;
    const int warp = tid >> 5;

    const size_t rowbase = (size_t)batch * S_;
    const int qcol = h * 384;
    const float* al = alibi + (size_t)bh * S_;
    const float inv = 0.08838834764831845f;

    const int ldR  = tid >> 4;         // 0..15
    const int ldCk = tid & 15;         // chunk 0..15

    auto load_q = [&]() {
#pragma unroll
        for (int i = 0; i < 8; i++) {
            int r = i * 16 + ldR;
            uint32_t dst = (uint32_t)r * 256 +
                (((uint32_t)ldCk ^ ((uint32_t)r & 7)) << 4);
            size_t goff = (rowbase + qt * 128 + r) * NQKV_ + qcol + ldCk * 8;
            cp_async16(Qs + dst, QKVh + goff);
        }
    };
    auto load_kv = [&](int j, int slot) {
        uint32_t stg = sb + ASTG_OFF + (uint32_t)slot * ASTG_SZ;
#pragma unroll
        for (int i = 0; i < 4; i++) {
            int r = i * 16 + ldR;
            uint32_t dst = (uint32_t)r * 256 +
                (((uint32_t)ldCk ^ ((uint32_t)r & 7)) << 4);
            size_t goff = (rowbase + j * 64 + r) * NQKV_ + qcol + ldCk * 8;
            cp_async16(stg +         dst, QKVh + goff + 128);   // Khi
            cp_async16(stg + 16384 + dst, QKVl + goff + 128);   // Klo
            cp_async16(stg + 32768 + dst, QKVh + goff + 256);   // Vhi
            cp_async16(stg + 49152 + dst, QKVl + goff + 256);   // Vlo
        }
    };

    const int jmax = 2 * qt + 1;
    load_q(); load_kv(0, 0); cp_commit();
    if (jmax >= 1) load_kv(1, 1);
    cp_commit();

    const int aRow = warp * 16 + (lane & 15);
    const uint32_t aChH = (uint32_t)(lane >> 4);
    const int bRowBase = (((lane >> 4) & 1) << 3) + (lane & 7);
    const uint32_t bChH = (uint32_t)((lane >> 3) & 1);
    const int vTok = (lane & 7) + (lane & 8);
    const int vD   = (lane >> 4) << 3;

    const int g  = lane >> 2;
    const int c2 = (lane & 3) * 2;
    const int qg0 = qt * 128 + warp * 16 + g;

    float O[16][4];
#pragma unroll
    for (int n = 0; n < 16; n++)
#pragma unroll
        for (int e = 0; e < 4; e++) O[n][e] = 0.f;
    float m0 = -1e30f, m1 = -1e30f, l0 = 0.f, l1 = 0.f;

    for (int j = 0; j <= jmax; j++) {
        cp_wait1();
        __syncthreads();

        uint32_t stg = sb + ASTG_OFF + (uint32_t)(j & 1) * ASTG_SZ;
        const uint32_t Kh = stg, Kl = stg + 16384;
        const uint32_t Vh = stg + 32768, Vl = stg + 49152;

        float S[8][4];
#pragma unroll
        for (int n = 0; n < 8; n++)
#pragma unroll
            for (int e = 0; e < 4; e++) S[n][e] = 0.f;

#pragma unroll
        for (int ks = 0; ks < 8; ks++) {
            uint32_t aOff = (uint32_t)aRow * 256 +
                (((2u * ks + aChH) ^ ((uint32_t)aRow & 7)) << 4);
            uint32_t av[4];
            ldsm4(av, Qs + aOff);
#pragma unroll
            for (int p = 0; p < 4; p++) {
                int bRow = p * 16 + bRowBase;
                uint32_t bOff = (uint32_t)bRow * 256 +
                    (((2u * ks + bChH) ^ ((uint32_t)bRow & 7)) << 4);
                uint32_t bhi[4], blo[4];
                ldsm4(bhi, Kh + bOff);
                ldsm4(blo, Kl + bOff);
#pragma unroll
                for (int q2 = 0; q2 < 2; q2++) {
                    int nt = p * 2 + q2;
                    mma_f16(S[nt], av, &bhi[q2 * 2]);
                    mma_f16(S[nt], av, &blo[q2 * 2]);
                }
            }
        }

        const bool diag = (j * 64 + 63 > qt * 128 + warp * 16);
#pragma unroll
        for (int nt = 0; nt < 8; nt++) {
            float2 a = *(const float2*)(al + j * 64 + nt * 8 + c2);
            S[nt][0] = S[nt][0] * inv + a.x;
            S[nt][1] = S[nt][1] * inv + a.y;
            S[nt][2] = S[nt][2] * inv + a.x;
            S[nt][3] = S[nt][3] * inv + a.y;
            if (diag) {
                int kg = j * 64 + nt * 8 + c2;
                if (kg     > qg0)     S[nt][0] = -1e30f;
                if (kg + 1 > qg0)     S[nt][1] = -1e30f;
                if (kg     > qg0 + 8) S[nt][2] = -1e30f;
                if (kg + 1 > qg0 + 8) S[nt][3] = -1e30f;
            }
        }

        float mx0 = -1e30f, mx1 = -1e30f;
#pragma unroll
        for (int nt = 0; nt < 8; nt++) {
            mx0 = fmaxf(mx0, fmaxf(S[nt][0], S[nt][1]));
            mx1 = fmaxf(mx1, fmaxf(S[nt][2], S[nt][3]));
        }
        mx0 = fmaxf(mx0, __shfl_xor_sync(0xffffffffu, mx0, 1));
        mx0 = fmaxf(mx0, __shfl_xor_sync(0xffffffffu, mx0, 2));
        mx1 = fmaxf(mx1, __shfl_xor_sync(0xffffffffu, mx1, 1));
        mx1 = fmaxf(mx1, __shfl_xor_sync(0xffffffffu, mx1, 2));
        float mn0 = fmaxf(m0, mx0), mn1 = fmaxf(m1, mx1);
        float sf0 = __expf(m0 - mn0), sf1 = __expf(m1 - mn1);
        float sum0 = 0.f, sum1 = 0.f;
#pragma unroll
        for (int nt = 0; nt < 8; nt++) {
            S[nt][0] = __expf(S[nt][0] - mn0); sum0 += S[nt][0];
            S[nt][1] = __expf(S[nt][1] - mn0); sum0 += S[nt][1];
            S[nt][2] = __expf(S[nt][2] - mn1); sum1 += S[nt][2];
            S[nt][3] = __expf(S[nt][3] - mn1); sum1 += S[nt][3];
        }
        sum0 += __shfl_xor_sync(0xffffffffu, sum0, 1);
        sum0 += __shfl_xor_sync(0xffffffffu, sum0, 2);
        sum1 += __shfl_xor_sync(0xffffffffu, sum1, 1);
        sum1 += __shfl_xor_sync(0xffffffffu, sum1, 2);
        l0 = l0 * sf0 + sum0; m0 = mn0;
        l1 = l1 * sf1 + sum1; m1 = mn1;
#pragma unroll
        for (int n = 0; n < 16; n++) {
            O[n][0] *= sf0; O[n][1] *= sf0;
            O[n][2] *= sf1; O[n][3] *= sf1;
        }

        // O += P V  (P single f16; V hi+lo)
#pragma unroll
        for (int ks = 0; ks < 4; ks++) {
            uint32_t pa[4];
            pa[0] = pack_f16(S[2 * ks][0],     S[2 * ks][1]);
            pa[1] = pack_f16(S[2 * ks][2],     S[2 * ks][3]);
            pa[2] = pack_f16(S[2 * ks + 1][0], S[2 * ks + 1][1]);
            pa[3] = pack_f16(S[2 * ks + 1][2], S[2 * ks + 1][3]);
            int tok = ks * 16 + vTok;
            uint32_t tRow = (uint32_t)tok * 256;
            uint32_t tSw  = (uint32_t)tok & 7;
#pragma unroll
            for (int nt16 = 0; nt16 < 8; nt16++) {
                int d = nt16 * 16 + vD;
                uint32_t vOff = tRow + ((((uint32_t)d >> 3) ^ tSw) << 4);
                uint32_t bvh[4], bvl[4];
                ldsm4t(bvh, Vh + vOff);
                ldsm4t(bvl, Vl + vOff);
                mma_f16(O[nt16 * 2],     pa, &bvh[0]);
                mma_f16(O[nt16 * 2 + 1], pa, &bvh[2]);
                mma_f16(O[nt16 * 2],     pa, &bvl[0]);
                mma_f16(O[nt16 * 2 + 1], pa, &bvl[2]);
            }
        }

        __syncthreads();
        if (j + 2 <= jmax) load_kv(j + 2, j & 1);
        cp_commit();
    }

    // epilogue: ctx = O / l, single f16 (A-side of dense GEMM)
    float il0 = 1.f / l0, il1 = 1.f / l1;
    size_t r0 = rowbase + qt * 128 + warp * 16 + g;
    size_t r1 = r0 + 8;
#pragma unroll
    for (int n = 0; n < 16; n++) {
        int col = h * 128 + n * 8 + c2;
        *(uint32_t*)(Ch + r0 * H_ + col) = pack_f16(O[n][0] * il0, O[n][1] * il0);
        *(uint32_t*)(Ch + r1 * H_ + col) = pack_f16(O[n][2] * il1, O[n][3] * il1);
    }
}

// ============================================================
// Launch: serial splits + QKV, then b0/b1 overlap (round-8 proven)
// ============================================================
extern "C" void kernel_launch(void* const* d_in, const int* in_sizes, int n_in,
                              void* d_out, int out_size)
{
    const float* hidden   = (const float*)d_in[0];
    const float* residual = (const float*)d_in[1];
    const float* alibi    = (const float*)d_in[2];
    const float* Wqkv     = (const float*)d_in[4];
    const float* bqkv     = (const float*)d_in[5];
    const float* Wd       = (const float*)d_in[6];
    const float* bd       = (const float*)d_in[7];
    float* out = (float*)d_out;

    void* p;
    cudaGetSymbolAddress(&p, g_QKVh); __half* QKVh = (__half*)p;
    cudaGetSymbolAddress(&p, g_QKVl); __half* QKVl = (__half*)p;
    cudaGetSymbolAddress(&p, g_Ah);   __half* Ah   = (__half*)p;
    cudaGetSymbolAddress(&p, g_Bqh);  __half* Bqh  = (__half*)p;
    cudaGetSymbolAddress(&p, g_Bql);  __half* Bql  = (__half*)p;
    cudaGetSymbolAddress(&p, g_Bdh);  __half* Bdh  = (__half*)p;
    cudaGetSymbolAddress(&p, g_Bdl);  __half* Bdl  = (__half*)p;
    cudaGetSymbolAddress(&p, g_Ch);   __half* Ch   = (__half*)p;

    cudaFuncSetAttribute(attn_mma, cudaFuncAttributeMaxDynamicSharedMemorySize, ATTN_SMEM);
    cudaFuncSetAttribute(mma_gemm<false, true>,
                         cudaFuncAttributeMaxDynamicSharedMemorySize, GSM_TOTAL);
    cudaFuncSetAttribute(mma_gemm<true, false>,
                         cudaFuncAttributeMaxDynamicSharedMemorySize, GSM_TOTAL);

    cudaStream_t s1;
    cudaStreamCreateWithFlags(&s1, cudaStreamNonBlocking);
    cudaEvent_t evQ, evE;
    cudaEventCreateWithFlags(&evQ, cudaEventDisableTiming);
    cudaEventCreateWithFlags(&evE, cudaEventDisableTiming);

    const size_t half = (size_t)S_ * H_;   // 1024 rows

    // serial: converts/splits then QKV projection (split f16 output)
    conv_rows<<<(M_ * H_ / 4 + 255) / 256, 256>>>(hidden, Ah, M_ * H_ / 4);
    split_transpose<<<dim3(NQKV_ / 32, H_ / 32), dim3(32, 8)>>>(Wqkv, Bqh, Bql, H_, NQKV_);
    split_transpose<<<dim3(H_ / 32, H_ / 32), dim3(32, 8)>>>(Wd, Bdh, Bdl, H_, H_);
    mma_gemm<false, true><<<dim3(M_ / 128, NQKV_ / 128), 256, GSM_TOTAL>>>(
        Ah, Bqh, Bql, bqkv, nullptr, nullptr, QKVh, QKVl, NQKV_, H_);
    cudaEventRecord(evQ, 0);

    // s1: batch-1 attention then batch-1 dense
    cudaStreamWaitEvent(s1, evQ, 0);
    attn_mma<<<dim3(8, 32), 256, ATTN_SMEM, s1>>>(QKVh, QKVl, alibi, Ch, 1);
    mma_gemm<true, false><<<dim3(8, H_ / 128), 256, GSM_TOTAL, s1>>>(
        Ch + half, Bdh, Bdl, bd, residual + half, out + half,
        nullptr, nullptr, H_, H_);
    cudaEventRecord(evE, s1);

    // main: batch-0 attention then batch-0 dense
    attn_mma<<<dim3(8, 32), 256, ATTN_SMEM>>>(QKVh, QKVl, alibi, Ch, 0);
    mma_gemm<true, false><<<dim3(8, H_ / 128), 256, GSM_TOTAL>>>(
        Ch, Bdh, Bdl, bd, residual, out, nullptr, nullptr, H_, H_);

    // join
    cudaStreamWaitEvent(0, evE, 0);
}